// round 12
// baseline (speedup 1.0000x reference)
#include <cuda_runtime.h>
#include <cstdint>
#include <stdint.h>

#define B_SZ   256
#define T_SZ   2048
#define N_SZ   128
#define NPAIRS (B_SZ * T_SZ)   // 524288

#define WROW   132
#define WROW4  33
#define BSROW  129

#define RNN_BLOCKS 8
#define CT     32              // timesteps per RNN chunk
#define NCH    (T_SZ / CT)     // 64

// Scratch (device globals — no allocation allowed)
__device__ __align__(16) float  g_h[NPAIRS * 2];  // hidden, [t][b] float2 layout
__device__ __align__(16) float2 g_c[NPAIRS];      // input proj, [t][b] float2
__device__ __align__(16) float  g_q0[N_SZ];       // Q[:,0]
__device__ __align__(16) float  g_q1[N_SZ];       // Q[:,1]

__device__ __forceinline__ float fast_rcp(float x) {
    float r;
    asm("rcp.approx.f32 %0, %1;" : "=f"(r) : "f"(x));
    return r;
}

// ---------------------------------------------------------------------------
// Kernel 0: input projection  c[t][b] = 0.1 * wIn @ u[b,t,:]
// ---------------------------------------------------------------------------
__global__ void __launch_bounds__(256) proj_kernel(const float* __restrict__ u,
                                                   const float* __restrict__ wIn) {
    const float I00 = 0.1f * __ldg(wIn + 0), I01 = 0.1f * __ldg(wIn + 1),
                I02 = 0.1f * __ldg(wIn + 2);
    const float I10 = 0.1f * __ldg(wIn + 3), I11 = 0.1f * __ldg(wIn + 4),
                I12 = 0.1f * __ldg(wIn + 5);

    int p4 = (int)blockIdx.x * 256 + (int)threadIdx.x;   // 0..131071
    int b  = p4 >> 9;
    int t0 = (p4 & 511) << 2;

    const float4* up = (const float4*)(u + (size_t)b * (T_SZ * 3) + (size_t)t0 * 3);
    float4 v0 = __ldg(up + 0);
    float4 v1 = __ldg(up + 1);
    float4 v2 = __ldg(up + 2);

    float2* outp = g_c + (size_t)t0 * B_SZ + b;
    outp[0]         = make_float2(fmaf(I00, v0.x, fmaf(I01, v0.y, I02 * v0.z)),
                                  fmaf(I10, v0.x, fmaf(I11, v0.y, I12 * v0.z)));
    outp[B_SZ]      = make_float2(fmaf(I00, v0.w, fmaf(I01, v1.x, I02 * v1.y)),
                                  fmaf(I10, v0.w, fmaf(I11, v1.x, I12 * v1.y)));
    outp[2 * B_SZ]  = make_float2(fmaf(I00, v1.z, fmaf(I01, v1.w, I02 * v2.x)),
                                  fmaf(I10, v1.z, fmaf(I11, v1.w, I12 * v2.x)));
    outp[3 * B_SZ]  = make_float2(fmaf(I00, v2.y, fmaf(I01, v2.z, I02 * v2.w)),
                                  fmaf(I10, v2.y, fmaf(I11, v2.z, I12 * v2.w)));
}

// ---------------------------------------------------------------------------
// Phase 1:
//   block 0:     Cayley solve — panel-4 blocked GE, warp-0 panel fact,
//                TWO block barriers per panel
//   blocks 1..8: leaky RNN — warp0 compute, warp1 c-prefetch, warps2-3 h-drain
// ---------------------------------------------------------------------------
__global__ void __launch_bounds__(256) phase1_kernel(
        const float* __restrict__ matB,
        const float* __restrict__ wRec) {
    extern __shared__ float smem[];
    const int tid  = threadIdx.x;
    const int lane = tid & 31;
    const int wid  = tid >> 5;

    if (blockIdx.x == 0) {
        // ================= Cayley solve =================
        float*  Wf     = smem;                           // [128][132]
        float4* W4     = (float4*)smem;                  // stride 33
        float*  Bs     = smem + N_SZ * WROW;             // [128][129]
        float*  prowf  = Bs + N_SZ * BSROW;              // [4][132]
        float4* prow4  = (float4*)prowf;                 // [4][33]
        float*  rinv_s = prowf + 4 * WROW;               // [4]
        __shared__ float z0s[N_SZ], z1s[N_SZ];
        const int i = tid;                               // row (threads 0..127)

        // ---- stage matB (coalesced float4) ----
        for (int idx = tid; idx < N_SZ * 32; idx += 256) {
            int r = idx >> 5, c4 = idx & 31;
            float4 v = ((const float4*)matB)[r * 32 + c4];
            float* dst = Bs + r * BSROW + c4 * 4;
            dst[0] = v.x; dst[1] = v.y; dst[2] = v.z; dst[3] = v.w;
        }
        __syncthreads();

        // ---- build augmented [I+A | e0 e1] ----
        if (i < N_SZ) {
            float* wr = Wf + i * WROW;
            #pragma unroll 4
            for (int j = 0; j < N_SZ; j++) {
                float a = Bs[i * BSROW + j] - Bs[j * BSROW + i];
                wr[j] = (i == j ? 1.0f : 0.0f) + a;
            }
            wr[128] = (i == 0) ? 1.0f : 0.0f;
            wr[129] = (i == 1) ? 1.0f : 0.0f;
            wr[130] = 0.0f; wr[131] = 0.0f;
        }
        __syncthreads();

        // ---- 32 panels, 2 barriers each ----
        for (int p = 0; p < 32; p++) {
            // ===== panel factorization: warp 0 only =====
            if (wid == 0) {
                const unsigned FULL = 0xffffffffu;
                float4 pr[4];      // this lane's group of each prow row
                float4 pr32[4];    // lane 0 only: group 32
                float  rv[4];
                #pragma unroll
                for (int m = 0; m < 4; m++) {
                    const int k = 4 * p + m;
                    float4 v   = W4[k * WROW4 + lane];
                    float4 v32 = make_float4(0.f, 0.f, 0.f, 0.f);
                    if (lane == 0) v32 = W4[k * WROW4 + 32];
                    #pragma unroll
                    for (int j = 0; j < 3; j++) {
                        if (j < m) {
                            float elem = (j == 0) ? v.x : ((j == 1) ? v.y : v.z);
                            float fj = __shfl_sync(FULL, elem * rv[j], p);
                            v.x = fmaf(-fj, pr[j].x, v.x);
                            v.y = fmaf(-fj, pr[j].y, v.y);
                            v.z = fmaf(-fj, pr[j].z, v.z);
                            v.w = fmaf(-fj, pr[j].w, v.w);
                            if (lane == 0) {
                                v32.x = fmaf(-fj, pr32[j].x, v32.x);
                                v32.y = fmaf(-fj, pr32[j].y, v32.y);
                                v32.z = fmaf(-fj, pr32[j].z, v32.z);
                                v32.w = fmaf(-fj, pr32[j].w, v32.w);
                            }
                        }
                    }
                    float dg = (m == 0) ? v.x : ((m == 1) ? v.y : ((m == 2) ? v.z : v.w));
                    float rm = __shfl_sync(FULL, fast_rcp(dg), p);
                    rv[m] = rm;
                    pr[m] = v;
                    prow4[m * WROW4 + lane] = v;
                    if (lane == 0) {
                        pr32[m] = v32;
                        prow4[m * WROW4 + 32] = v32;
                        rinv_s[m] = rm;
                    }
                }
            }
            __syncthreads();   // bar 1: prow + rinv published

            // ===== factors in registers + rank-4 update (rows below panel) ====
            if (i < N_SZ && i > 4 * p + 3) {
                float4 cp  = W4[i * WROW4 + p];
                float4 pp0 = prow4[0 * WROW4 + p];
                float4 pp1 = prow4[1 * WROW4 + p];
                float4 pp2 = prow4[2 * WROW4 + p];
                float r0 = rinv_s[0], r1 = rinv_s[1], r2 = rinv_s[2], r3 = rinv_s[3];

                float f0 = cp.x * r0;
                cp.y = fmaf(-f0, pp0.y, cp.y);
                float f1 = cp.y * r1;
                cp.z = fmaf(-f1, pp1.z, fmaf(-f0, pp0.z, cp.z));
                float f2 = cp.z * r2;
                cp.w = fmaf(-f2, pp2.w, fmaf(-f1, pp1.w, fmaf(-f0, pp0.w, cp.w)));
                float f3 = cp.w * r3;

                const float4* q0r = prow4 + 0 * WROW4;
                const float4* q1r = prow4 + 1 * WROW4;
                const float4* q2r = prow4 + 2 * WROW4;
                const float4* q3r = prow4 + 3 * WROW4;
                float4* wr = W4 + i * WROW4;
                #pragma unroll 4
                for (int g = p + 1; g < WROW4; g++) {
                    float4 a  = wr[g];
                    float4 q0 = q0r[g], q1 = q1r[g], q2 = q2r[g], q3 = q3r[g];
                    a.x = fmaf(-f0, q0.x, fmaf(-f1, q1.x, fmaf(-f2, q2.x, fmaf(-f3, q3.x, a.x))));
                    a.y = fmaf(-f0, q0.y, fmaf(-f1, q1.y, fmaf(-f2, q2.y, fmaf(-f3, q3.y, a.y))));
                    a.z = fmaf(-f0, q0.z, fmaf(-f1, q1.z, fmaf(-f2, q2.z, fmaf(-f3, q3.z, a.z))));
                    a.w = fmaf(-f0, q0.w, fmaf(-f1, q1.w, fmaf(-f2, q2.w, fmaf(-f3, q3.w, a.w))));
                    wr[g] = a;
                }
            }
            // copyback of finalized pivot rows by the idle upper half
            if (tid >= 128) {
                for (int idx = tid - 128; idx < 4 * WROW4; idx += 128)
                    W4[(4 * p + idx / WROW4) * WROW4 + (idx % WROW4)] = prow4[idx];
            }
            __syncthreads();   // bar 2: panel complete
        }

        // ---- back substitution (2 RHS) ----
        for (int k = N_SZ - 1; k >= 0; k--) {
            if (i < N_SZ) {
                float rinv = fast_rcp(Wf[k * WROW + k]);
                float zk0 = Wf[k * WROW + 128] * rinv;
                float zk1 = Wf[k * WROW + 129] * rinv;
                if (i < k) {
                    float a = Wf[i * WROW + k];
                    Wf[i * WROW + 128] = fmaf(-a, zk0, Wf[i * WROW + 128]);
                    Wf[i * WROW + 129] = fmaf(-a, zk1, Wf[i * WROW + 129]);
                } else if (i == k) {
                    z0s[k] = zk0;
                    z1s[k] = zk1;
                }
            }
            __syncthreads();
        }

        // ---- q_r = (I - A) z_r ----
        if (i < N_SZ) {
            float q0 = z0s[i], q1 = z1s[i];
            #pragma unroll 4
            for (int k = 0; k < N_SZ; k++) {
                float a = Bs[i * BSROW + k] - Bs[k * BSROW + i];
                q0 = fmaf(-a, z0s[k], q0);
                q1 = fmaf(-a, z1s[k], q1);
            }
            g_q0[i] = q0;
            g_q1[i] = q1;
        }
    } else {
        // ====== Leaky RNN: warp-specialized smem pipeline ======
        if (wid >= 4) return;                       // warps 4-7 unused
        const int seqBase = ((int)blockIdx.x - 1) * 32;

        float2* cbuf = (float2*)smem;               // [2][32][32]
        float2* hbuf = cbuf + 2 * CT * 32;          // [2][32][32]
        float2* hp   = (float2*)g_h;
        const float2* gc = g_c;

        #define RNN_BAR() asm volatile("bar.sync 1, 128;" ::: "memory")

        if (wid == 1) {
            // prologue: fill cbuf[0] with chunk 0
            const float2* src = gc + seqBase + lane;
            float2* dst = cbuf + lane;
            #pragma unroll
            for (int s = 0; s < CT; s++)
                dst[s * 32] = __ldg(src + (size_t)s * B_SZ);
        }
        RNN_BAR();

        if (wid == 0) {
            // ---- compute warp ----
            const float W00 = 0.1f * wRec[0], W01 = 0.1f * wRec[1];
            const float W10 = 0.1f * wRec[2], W11 = 0.1f * wRec[3];
            float y0 = 0.0f, y1 = 0.0f;

            for (int ch = 0; ch < NCH; ch++) {
                const float2* cb = cbuf + (ch & 1) * (CT * 32) + lane;
                float2*       hb = hbuf + (ch & 1) * (CT * 32) + lane;
                #pragma unroll
                for (int s = 0; s < CT; s++) {
                    float2 c = cb[s * 32];
                    float a0 = fmaf(0.9f, y0, c.x);
                    float a1 = fmaf(0.9f, y1, c.y);
                    float r0 = fmaxf(y0, 0.0f);
                    float r1 = fmaxf(y1, 0.0f);
                    float t0 = fmaf(W00, r0, a0);
                    float t1 = fmaf(W10, r0, a1);
                    y0 = fmaf(W01, r1, t0);
                    y1 = fmaf(W11, r1, t1);
                    hb[s * 32] = make_float2(y0, y1);
                }
                RNN_BAR();
            }
        } else if (wid == 1) {
            // ---- c prefetch warp ----
            for (int ch = 0; ch < NCH; ch++) {
                if (ch + 1 < NCH) {
                    const float2* src = gc + (size_t)(ch + 1) * CT * B_SZ + seqBase + lane;
                    float2* dst = cbuf + ((ch + 1) & 1) * (CT * 32) + lane;
                    #pragma unroll
                    for (int s = 0; s < CT; s++)
                        dst[s * 32] = __ldg(src + (size_t)s * B_SZ);
                }
                RNN_BAR();
            }
        } else {
            // ---- h drain warps (wid 2: rows 0-15, wid 3: rows 16-31) ----
            const int rbase = (wid - 2) * 16;
            for (int ch = 0; ch < NCH; ch++) {
                if (ch > 0) {
                    const float2* src = hbuf + ((ch - 1) & 1) * (CT * 32) + lane;
                    float2* dst = hp + (size_t)(ch - 1) * CT * B_SZ + seqBase + lane;
                    #pragma unroll
                    for (int r = 0; r < 16; r++) {
                        int s = rbase + r;
                        dst[(size_t)s * B_SZ] = src[s * 32];
                    }
                }
                RNN_BAR();
            }
            // epilogue: drain chunk 63 from hbuf[1]
            {
                const float2* src = hbuf + 1 * (CT * 32) + lane;
                float2* dst = hp + (size_t)(NCH - 1) * CT * B_SZ + seqBase + lane;
                #pragma unroll
                for (int r = 0; r < 16; r++) {
                    int s = rbase + r;
                    dst[(size_t)s * B_SZ] = src[s * 32];
                }
            }
        }
        #undef RNN_BAR
    }
}

// ---------------------------------------------------------------------------
// Phase 2: out[b,t,:] = h0 * q0[:] + h1 * q1[:]
// ---------------------------------------------------------------------------
__global__ void __launch_bounds__(256, 8) expand_kernel(float* __restrict__ out) {
    const int lane = threadIdx.x & 31;
    const int wid  = ((int)blockIdx.x * (int)blockDim.x + (int)threadIdx.x) >> 5;
    const int nw   = ((int)gridDim.x * (int)blockDim.x) >> 5;

    const float4 q0 = ((const float4*)g_q0)[lane];
    const float4 q1 = ((const float4*)g_q1)[lane];
    const float2* hp = (const float2*)g_h;
    float4* o = (float4*)out;

    const int ntask = NPAIRS / 4;
    for (int task = wid; task < ntask; task += nw) {
        int q = task << 2;          // q = b*2048 + t
        int b = q >> 11;
        int t = q & (T_SZ - 1);

        float2 h0 = hp[(t + 0) * B_SZ + b];
        float2 h1 = hp[(t + 1) * B_SZ + b];
        float2 h2 = hp[(t + 2) * B_SZ + b];
        float2 h3 = hp[(t + 3) * B_SZ + b];

        size_t base = (size_t)q * 32 + lane;
        float4 v;
        v.x = fmaf(h0.x, q0.x, h0.y * q1.x);
        v.y = fmaf(h0.x, q0.y, h0.y * q1.y);
        v.z = fmaf(h0.x, q0.z, h0.y * q1.z);
        v.w = fmaf(h0.x, q0.w, h0.y * q1.w);
        __stcs(&o[base], v);
        v.x = fmaf(h1.x, q0.x, h1.y * q1.x);
        v.y = fmaf(h1.x, q0.y, h1.y * q1.y);
        v.z = fmaf(h1.x, q0.z, h1.y * q1.z);
        v.w = fmaf(h1.x, q0.w, h1.y * q1.w);
        __stcs(&o[base + 32], v);
        v.x = fmaf(h2.x, q0.x, h2.y * q1.x);
        v.y = fmaf(h2.x, q0.y, h2.y * q1.y);
        v.z = fmaf(h2.x, q0.z, h2.y * q1.z);
        v.w = fmaf(h2.x, q0.w, h2.y * q1.w);
        __stcs(&o[base + 64], v);
        v.x = fmaf(h3.x, q0.x, h3.y * q1.x);
        v.y = fmaf(h3.x, q0.y, h3.y * q1.y);
        v.z = fmaf(h3.x, q0.z, h3.y * q1.z);
        v.w = fmaf(h3.x, q0.w, h3.y * q1.w);
        __stcs(&o[base + 96], v);
    }
}

// ---------------------------------------------------------------------------
extern "C" void kernel_launch(void* const* d_in, const int* in_sizes, int n_in,
                              void* d_out, int out_size) {
    // u = 1572864, matB = 16384, wIn = 6, wRec = 4
    const float *u = nullptr, *matB = nullptr, *wIn = nullptr, *wRec = nullptr;
    for (int i = 0; i < n_in; i++) {
        switch (in_sizes[i]) {
            case 1572864: u    = (const float*)d_in[i]; break;
            case 16384:   matB = (const float*)d_in[i]; break;
            case 6:       wIn  = (const float*)d_in[i]; break;
            case 4:       wRec = (const float*)d_in[i]; break;
        }
    }

    // W + Bs + prow + rinv  (RNN path needs only 32KB of this)
    const int smem = (N_SZ * WROW + N_SZ * BSROW + 4 * WROW + 4)
                     * (int)sizeof(float);   // ~135.8 KB
    cudaFuncSetAttribute(phase1_kernel,
                         cudaFuncAttributeMaxDynamicSharedMemorySize, smem);

    // 0) input projection: u -> g_c
    proj_kernel<<<512, 256>>>(u, wIn);

    // 1) block 0: solve;  blocks 1..8: RNN (compute/prefetch/drain warps)
    phase1_kernel<<<1 + RNN_BLOCKS, 256, smem>>>(matB, wRec);

    // 2) expand: write-bandwidth bound
    expand_kernel<<<1184, 256>>>((float*)d_out);
}